// round 5
// baseline (speedup 1.0000x reference)
#include <cuda_runtime.h>
#include <cuda_bf16.h>
#include <math.h>
#include <stdint.h>

#define E_DIM 512
#define BLROWS 16384
#define NRR 100
#define NPAD 112                        // 14 n-tiles of 8
#define NORM_TERM 10.82490511970208f    // ln(50257)
#define LOG_NR 4.605170185988092f       // ln(100)
#define ASTR 144                        // A smem row stride bytes (72 bf16)
#define ABUF 18432                      // 128*144 per A stage
#define BSTR 1040                       // B smem row stride bytes (520 bf16)

__device__ float g_part[128];
__device__ int   g_ctr = 0;             // self-resetting (graph-replay safe)

__device__ __forceinline__ uint32_t smem_u32(const void* p) {
    uint32_t a;
    asm("{ .reg .u64 t; cvta.to.shared.u64 t, %1; cvt.u32.u64 %0, t; }" : "=r"(a) : "l"(p));
    return a;
}
__device__ __forceinline__ void ldmatrix_x4(uint32_t& r0, uint32_t& r1,
                                            uint32_t& r2, uint32_t& r3, uint32_t addr) {
    asm volatile("ldmatrix.sync.aligned.m8n8.x4.shared.b16 {%0,%1,%2,%3}, [%4];"
                 : "=r"(r0), "=r"(r1), "=r"(r2), "=r"(r3) : "r"(addr));
}
__device__ __forceinline__ void mma16816(float* d, const uint32_t* a,
                                         uint32_t b0, uint32_t b1) {
    asm volatile("mma.sync.aligned.m16n8k16.row.col.f32.bf16.bf16.f32 "
                 "{%0,%1,%2,%3}, {%4,%5,%6,%7}, {%8,%9}, {%0,%1,%2,%3};"
                 : "+f"(d[0]), "+f"(d[1]), "+f"(d[2]), "+f"(d[3])
                 : "r"(a[0]), "r"(a[1]), "r"(a[2]), "r"(a[3]), "r"(b0), "r"(b1));
}
__device__ __forceinline__ float softplus_exact(float x) {
    return fmaxf(x, 0.0f) + log1pf(expf(-fabsf(x)));
}
__device__ __forceinline__ uint2 cvt_bf16x4(float4 v) {
    __nv_bfloat162 p0 = __float22bfloat162_rn(make_float2(v.x, v.y));
    __nv_bfloat162 p1 = __float22bfloat162_rn(make_float2(v.z, v.w));
    uint2 r;
    r.x = *reinterpret_cast<uint32_t*>(&p0);
    r.y = *reinterpret_cast<uint32_t*>(&p1);
    return r;
}

// ---------------------------------------------------------------------------
// Warp-specialized fused kernel. 512 threads:
//   warps 0-7  consumers: MMA only. warp w owns M-slab w*16, all 14 n-tiles.
//   warps 8-15 producers: LDG input + target-gather, f32->bf16 STS, exact dot.
// 2 A stages; consumers lag producers by 1 chunk; 9 lockstep iterations.
// ---------------------------------------------------------------------------
__global__ void __launch_bounds__(512, 1)
mega_kernel(const float* __restrict__ inp,
            const float* __restrict__ emb,
            const float* __restrict__ bias,
            const float* __restrict__ lpn,
            const int*   __restrict__ tgt,
            const int*   __restrict__ nidx,
            float* __restrict__ out) {
    extern __shared__ char dsm[];
    __shared__ float cs[NPAD];
    __shared__ int   s_n[NPAD];
    __shared__ int   s_t[128];
    __shared__ float s_xc[128];
    __shared__ float s_tdot[128];
    __shared__ float s_red[128];
    __shared__ float s_fin[128];

    const int tid = threadIdx.x;
    const int lane = tid & 31;
    const int row0 = blockIdx.x * 128;

    const uint32_t db = smem_u32(dsm);
    const uint32_t abase = (db + 1023u) & ~1023u;
    const uint32_t bbase = abase + 2 * ABUF;
    char* ap = dsm + (abase - db);
    char* bp = ap + 2 * ABUF;

    if (tid < NPAD) {
        int nv = (tid < NRR) ? nidx[tid] : -1;
        s_n[tid] = nv;
        cs[tid] = (tid < NRR) ? (bias[nv] - NORM_TERM - lpn[nv] - LOG_NR) : -1e30f;
    }
    if (tid >= 128 && tid < 256) {
        int r = tid - 128;
        int t = tgt[row0 + r];
        s_t[r] = t;
        s_xc[r] = bias[t] - NORM_TERM - lpn[t] - LOG_NR;
    }
    __syncthreads();

    // ---------------- role state ----------------
    // producers (tid >= 256)
    const int ptid = tid - 256;
    const int l4 = ptid & 15;           // 16B k-slot
    const int rg = ptid >> 4;           // 0..15; rows rg+16i
    const float* ipt = inp + (size_t)(row0 + rg) * E_DIM + l4 * 4;
    uint32_t eoff[8];
    float tacc[8];
    float4 va[8], ve[8];
    // consumers (tid < 256)
    const int m0 = (tid >> 5) * 16;
    const uint32_t a_woff = (uint32_t)(m0 + (lane & 15)) * ASTR + ((lane >> 4) << 4);
    const uint32_t b_off = bbase + (uint32_t)((lane & 7) + ((lane >> 4) << 3)) * BSTR
                                 + (((lane >> 3) & 1) << 4);
    float acc[14][4];

    if (tid >= 256) {
#pragma unroll
        for (int i = 0; i < 8; i++) {
            eoff[i] = (uint32_t)s_t[rg + 16 * i] * (E_DIM * 4);
            tacc[i] = 0.f;
        }
        // issue chunk 0 loads (input + gather) before the B fill
#pragma unroll
        for (int i = 0; i < 8; i++) {
            va[i] = *(const float4*)(ipt + i * 8192);
            ve[i] = *(const float4*)((const char*)emb + eoff[i] + (size_t)l4 * 16);
        }
    } else {
#pragma unroll
        for (int n = 0; n < 14; n++)
#pragma unroll
            for (int j = 0; j < 4; j++) acc[n][j] = 0.f;
    }

    // --- B fill (all 512 threads): gather noise emb -> bf16 [n][k] ---
    for (int idx = tid; idx < NPAD * 128; idx += 512) {
        int n = idx >> 7;
        int q = idx & 127;
        int t = s_n[n];
        float4 v = make_float4(0.f, 0.f, 0.f, 0.f);
        if (t >= 0) v = *(const float4*)(emb + (size_t)t * E_DIM + q * 4);
        *(uint2*)(bp + n * BSTR + q * 8) = cvt_bf16x4(v);
    }
    __syncthreads();

    // ---------------- main lockstep loop: 9 iterations ----------------
    for (int c = 0; c < 9; c++) {
        if (tid >= 256) {
            if (c <= 7) {
                // STS convert chunk c into stage c&1
                char* dst = ap + (c & 1) * ABUF + rg * ASTR + l4 * 8;
#pragma unroll
                for (int i = 0; i < 8; i++)
                    *(uint2*)(dst + i * (16 * ASTR)) = cvt_bf16x4(va[i]);
                // exact target-dot partials for chunk c
#pragma unroll
                for (int i = 0; i < 8; i++)
                    tacc[i] += va[i].x * ve[i].x + va[i].y * ve[i].y
                             + va[i].z * ve[i].z + va[i].w * ve[i].w;
                // issue chunk c+1 loads
                if (c < 7) {
#pragma unroll
                    for (int i = 0; i < 8; i++) {
                        va[i] = *(const float4*)(ipt + (c + 1) * 64 + i * 8192);
                        ve[i] = *(const float4*)((const char*)emb + eoff[i]
                                  + (size_t)((c + 1) * 64 + l4 * 4) * 4);
                    }
                }
            }
        } else if (c >= 1) {
            // MMA chunk c-1 from stage (c-1)&1
            const uint32_t ab = abase + (uint32_t)((c - 1) & 1) * ABUF + a_woff;
            const uint32_t bb = b_off + (uint32_t)(c - 1) * 128;
#pragma unroll
            for (int k0 = 0; k0 < 4; k0++) {
                uint32_t a[4];
                ldmatrix_x4(a[0], a[1], a[2], a[3], ab + k0 * 32);
#pragma unroll
                for (int nt = 0; nt < 7; nt++) {
                    uint32_t b0, b1, b2, b3;
                    ldmatrix_x4(b0, b1, b2, b3, bb + nt * (16 * BSTR) + k0 * 32);
                    mma16816(acc[nt * 2], a, b0, b1);
                    mma16816(acc[nt * 2 + 1], a, b2, b3);
                }
            }
        }
        __syncthreads();
    }

    // ---------------- epilogues ----------------
    if (tid >= 256) {
        // finish exact target dots: reduce over the 16 k-slot lanes per row
#pragma unroll
        for (int i = 0; i < 8; i++) {
            float v = tacc[i];
            v += __shfl_xor_sync(0xFFFFFFFFu, v, 8);
            v += __shfl_xor_sync(0xFFFFFFFFu, v, 4);
            v += __shfl_xor_sync(0xFFFFFFFFu, v, 2);
            v += __shfl_xor_sync(0xFFFFFFFFu, v, 1);
            if (l4 == 0) s_tdot[rg + 16 * i] = v;
        }
    } else {
        // softplus epilogue (product trick; x <= -1.8 always)
        const int g = lane >> 2;
        const int tq = lane & 3;
        float plo = 1.f, phi = 1.f;
#pragma unroll
        for (int nt = 0; nt < 14; nt++) {
            float c0 = cs[nt * 8 + 2 * tq];
            float c1 = cs[nt * 8 + 2 * tq + 1];
            plo *= (1.f + __expf(acc[nt][0] + c0));
            plo *= (1.f + __expf(acc[nt][1] + c1));
            phi *= (1.f + __expf(acc[nt][2] + c0));
            phi *= (1.f + __expf(acc[nt][3] + c1));
        }
        float slo = __logf(plo);
        float shi = __logf(phi);
        slo += __shfl_xor_sync(0xFFFFFFFFu, slo, 1);
        slo += __shfl_xor_sync(0xFFFFFFFFu, slo, 2);
        shi += __shfl_xor_sync(0xFFFFFFFFu, shi, 1);
        shi += __shfl_xor_sync(0xFFFFFFFFu, shi, 2);
        if (tq == 0) {
            s_red[m0 + g] = slo;
            s_red[m0 + g + 8] = shi;
        }
    }
    __syncthreads();

    // --- per-row combine (+ target slot), fixed-order block + grid reduce ---
    if (tid < 128) {
        float x0 = s_tdot[tid] + s_xc[tid];
        s_fin[tid] = s_red[tid] + softplus_exact(x0) - x0;
    }
    __syncthreads();
    if (tid < 32) {
        float s = s_fin[tid] + s_fin[tid + 32] + s_fin[tid + 64] + s_fin[tid + 96];
        s += __shfl_xor_sync(0xFFFFFFFFu, s, 16);
        s += __shfl_xor_sync(0xFFFFFFFFu, s, 8);
        s += __shfl_xor_sync(0xFFFFFFFFu, s, 4);
        s += __shfl_xor_sync(0xFFFFFFFFu, s, 2);
        s += __shfl_xor_sync(0xFFFFFFFFu, s, 1);
        if (tid == 0) {
            g_part[blockIdx.x] = s;
            __threadfence();
            int old = atomicAdd(&g_ctr, 1);
            if (old == 127) {
                __threadfence();
                float tot = 0.f;
#pragma unroll 1
                for (int r = 0; r < 128; r++)
                    tot += *((volatile float*)&g_part[r]);
                out[0] = tot * (1.0f / (float)BLROWS);
                g_ctr = 0;
            }
        }
    }
}

// ---------------------------------------------------------------------------
extern "C" void kernel_launch(void* const* d_in, const int* in_sizes, int n_in,
                              void* d_out, int out_size) {
    const float* inp  = (const float*)d_in[0];
    const float* emb  = (const float*)d_in[1];
    const float* bias = (const float*)d_in[2];
    const float* lpn  = (const float*)d_in[3];
    const int*   tgt  = (const int*)  d_in[4];
    const int*   nidx = (const int*)  d_in[5];
    float* out = (float*)d_out;

    const int DSM = 1024 + 2 * ABUF + NPAD * BSTR;   // 154368 B
    cudaFuncSetAttribute(mega_kernel, cudaFuncAttributeMaxDynamicSharedMemorySize, DSM);
    mega_kernel<<<128, 512, DSM>>>(inp, emb, bias, lpn, tgt, nidx, out);
}

// round 6
// speedup vs baseline: 2.2184x; 2.2184x over previous
#include <cuda_runtime.h>
#include <cuda_bf16.h>
#include <math.h>
#include <stdint.h>

#define E_DIM 512
#define BLROWS 16384
#define NRR 100
#define NPAD 112                        // 14 n-tiles of 8
#define NORM_TERM 10.82490511970208f    // ln(50257)
#define LOG_NR 4.605170185988092f       // ln(100)
#define MROWS 64                        // rows per CTA
#define ASTR 144                        // smem row stride (72 bf16)
#define ASTAGE (MROWS * ASTR)           // 9216
#define BSTAGE (NPAD * ASTR)            // 16128
#define NBLK 256                        // grid size

__device__ float g_part[NBLK];
__device__ int   g_ctr = 0;             // self-resetting (graph-replay safe)

__device__ __forceinline__ uint32_t smem_u32(const void* p) {
    uint32_t a;
    asm("{ .reg .u64 t; cvta.to.shared.u64 t, %1; cvt.u32.u64 %0, t; }" : "=r"(a) : "l"(p));
    return a;
}
__device__ __forceinline__ void ldmatrix_x4(uint32_t& r0, uint32_t& r1,
                                            uint32_t& r2, uint32_t& r3, uint32_t addr) {
    asm volatile("ldmatrix.sync.aligned.m8n8.x4.shared.b16 {%0,%1,%2,%3}, [%4];"
                 : "=r"(r0), "=r"(r1), "=r"(r2), "=r"(r3) : "r"(addr));
}
__device__ __forceinline__ void ldmatrix_x2(uint32_t& r0, uint32_t& r1, uint32_t addr) {
    asm volatile("ldmatrix.sync.aligned.m8n8.x2.shared.b16 {%0,%1}, [%2];"
                 : "=r"(r0), "=r"(r1) : "r"(addr));
}
__device__ __forceinline__ void mma16816(float* d, const uint32_t* a,
                                         uint32_t b0, uint32_t b1) {
    asm volatile("mma.sync.aligned.m16n8k16.row.col.f32.bf16.bf16.f32 "
                 "{%0,%1,%2,%3}, {%4,%5,%6,%7}, {%8,%9}, {%0,%1,%2,%3};"
                 : "+f"(d[0]), "+f"(d[1]), "+f"(d[2]), "+f"(d[3])
                 : "r"(a[0]), "r"(a[1]), "r"(a[2]), "r"(a[3]), "r"(b0), "r"(b1));
}
__device__ __forceinline__ float softplus_exact(float x) {
    return fmaxf(x, 0.0f) + log1pf(expf(-fabsf(x)));
}
__device__ __forceinline__ uint2 cvt_bf16x4(float4 v) {
    __nv_bfloat162 p0 = __float22bfloat162_rn(make_float2(v.x, v.y));
    __nv_bfloat162 p1 = __float22bfloat162_rn(make_float2(v.z, v.w));
    uint2 r;
    r.x = *reinterpret_cast<uint32_t*>(&p0);
    r.y = *reinterpret_cast<uint32_t*>(&p1);
    return r;
}

// ---------------------------------------------------------------------------
// 64-row CTAs, 256 threads, 2 CTAs/SM. All warps load+convert+MMA.
// Per iter: STS chunk c (loads from prev iter), LDG chunk c+1, barrier, MMA c.
// 2 smem stages for A and for B (B refetched from L2-hot gmem per chunk).
// ---------------------------------------------------------------------------
__global__ void __launch_bounds__(256, 2)
mega_kernel(const float* __restrict__ inp,
            const float* __restrict__ emb,
            const float* __restrict__ bias,
            const float* __restrict__ lpn,
            const int*   __restrict__ tgt,
            const int*   __restrict__ nidx,
            float* __restrict__ out) {
    extern __shared__ char dsm[];
    __shared__ float cs[NPAD];
    __shared__ int   s_n[NPAD];
    __shared__ int   s_t[MROWS];
    __shared__ float s_xc[MROWS];
    __shared__ float s_tdot[MROWS];
    __shared__ float s_red[2][MROWS];
    __shared__ float s_fin[MROWS];
    __shared__ int   s_flag;

    const int tid = threadIdx.x;
    const int lane = tid & 31;
    const int row0 = blockIdx.x * MROWS;

    const uint32_t db = smem_u32(dsm);
    const uint32_t abase = (db + 1023u) & ~1023u;
    const uint32_t bbase = abase + 2 * ASTAGE;
    char* ap = dsm + (abase - db);
    char* bp = ap + 2 * ASTAGE;

    if (tid < NPAD) {
        int nv = (tid < NRR) ? nidx[tid] : -1;
        s_n[tid] = nv;
        cs[tid] = (tid < NRR) ? (bias[nv] - NORM_TERM - lpn[nv] - LOG_NR) : -1e30f;
    }
    if (tid >= 128 && tid < 128 + MROWS) {
        int r = tid - 128;
        int t = tgt[row0 + r];
        s_t[r] = t;
        s_xc[r] = bias[t] - NORM_TERM - lpn[t] - LOG_NR;
    }
    __syncthreads();

    // ---------------- per-thread layout ----------------
    const int l4 = tid & 15;            // 16B k-slot
    const int rg = tid >> 4;            // 0..15
    const float* ipt = inp + (size_t)(row0 + rg) * E_DIM + l4 * 4;   // rows rg+16i
    const float* ept[4];
#pragma unroll
    for (int i = 0; i < 4; i++)
        ept[i] = emb + (size_t)s_t[rg + 16 * i] * E_DIM + l4 * 4;
    // B fill: rows rg+16i for i<7 (covers 0..111), slot l4
    const float* bpt[7];
#pragma unroll
    for (int i = 0; i < 7; i++) {
        int t = s_n[rg + 16 * i];
        bpt[i] = (t >= 0) ? (emb + (size_t)t * E_DIM + l4 * 4) : 0;
    }
    const uint32_t asts = rg * ASTR + l4 * 8;     // within A stage
    const uint32_t bsts = rg * ASTR + l4 * 8;     // within B stage (same form)

    // MMA fragment addressing (proven mapping)
    const int m0 = (tid >> 5 & 3) * 16;           // M-slab
    const int ngrp = tid >> 7;                    // n-half: 7 tiles each
    const uint32_t a_woff = (uint32_t)(m0 + (lane & 15)) * ASTR + ((lane >> 4) << 4);
    const uint32_t b_woff = (uint32_t)(ngrp * 56 + (lane & 7) + ((lane >> 4) << 3)) * ASTR
                          + (((lane >> 3) & 1) << 4);
    const uint32_t b2_woff = (uint32_t)(ngrp * 56 + 48 + (lane & 7)) * ASTR
                           + (((lane >> 3) & 1) << 4);

    float acc[7][4];
#pragma unroll
    for (int n = 0; n < 7; n++)
#pragma unroll
        for (int j = 0; j < 4; j++) acc[n][j] = 0.f;
    float tacc[4] = {0.f, 0.f, 0.f, 0.f};

    float4 va[4], ve[4], vb[7];
    // prologue: issue chunk-0 loads
#pragma unroll
    for (int i = 0; i < 4; i++) {
        va[i] = *(const float4*)(ipt + i * (16 * E_DIM));
        ve[i] = *(const float4*)(ept[i]);
    }
#pragma unroll
    for (int i = 0; i < 7; i++)
        vb[i] = bpt[i] ? *(const float4*)(bpt[i]) : make_float4(0.f, 0.f, 0.f, 0.f);

    // ---------------- main loop: 8 chunks of K=64 ----------------
#pragma unroll
    for (int c = 0; c < 8; c++) {
        const int st = c & 1;
        // STS chunk c (A convert + target-dot FMAs + B convert)
        {
            char* adst = ap + st * ASTAGE + asts;
            char* bdst = bp + st * BSTAGE + bsts;
#pragma unroll
            for (int i = 0; i < 4; i++) {
                tacc[i] += va[i].x * ve[i].x + va[i].y * ve[i].y
                         + va[i].z * ve[i].z + va[i].w * ve[i].w;
                *(uint2*)(adst + i * (16 * ASTR)) = cvt_bf16x4(va[i]);
            }
#pragma unroll
            for (int i = 0; i < 7; i++)
                *(uint2*)(bdst + i * (16 * ASTR)) = cvt_bf16x4(vb[i]);
        }
        // issue chunk c+1 loads (land during barrier + MMA below)
        if (c < 7) {
            const int ko = (c + 1) * 64;
#pragma unroll
            for (int i = 0; i < 4; i++) {
                va[i] = *(const float4*)(ipt + ko + i * (16 * E_DIM));
                ve[i] = *(const float4*)(ept[i] + ko);
            }
#pragma unroll
            for (int i = 0; i < 7; i++)
                vb[i] = bpt[i] ? *(const float4*)(bpt[i] + ko)
                               : make_float4(0.f, 0.f, 0.f, 0.f);
        }
        __syncthreads();
        // MMA chunk c from stage st
        {
            const uint32_t ab = abase + st * ASTAGE + a_woff;
            const uint32_t bb = bbase + st * BSTAGE + b_woff;
            const uint32_t bb2 = bbase + st * BSTAGE + b2_woff;
#pragma unroll
            for (int k0 = 0; k0 < 4; k0++) {
                uint32_t a[4];
                ldmatrix_x4(a[0], a[1], a[2], a[3], ab + k0 * 32);
#pragma unroll
                for (int p = 0; p < 3; p++) {
                    uint32_t b0, b1, b2, b3;
                    ldmatrix_x4(b0, b1, b2, b3, bb + p * (16 * ASTR) + k0 * 32);
                    mma16816(acc[p * 2], a, b0, b1);
                    mma16816(acc[p * 2 + 1], a, b2, b3);
                }
                uint32_t b0, b1;
                ldmatrix_x2(b0, b1, bb2 + k0 * 32);
                mma16816(acc[6], a, b0, b1);
            }
        }
        __syncthreads();   // stage st reusable only after all warps finish MMA c
    }

    // --- finish exact target dots (reduce over the 16 k-slot lanes) ---
#pragma unroll
    for (int i = 0; i < 4; i++) {
        float v = tacc[i];
        v += __shfl_xor_sync(0xFFFFFFFFu, v, 8);
        v += __shfl_xor_sync(0xFFFFFFFFu, v, 4);
        v += __shfl_xor_sync(0xFFFFFFFFu, v, 2);
        v += __shfl_xor_sync(0xFFFFFFFFu, v, 1);
        if (l4 == 0) s_tdot[rg + 16 * i] = v;
    }

    // --- softplus epilogue (product trick; noise x <= -1.8 always) ---
    {
        const int g = lane >> 2;
        const int tq = lane & 3;
        float plo = 1.f, phi = 1.f;
#pragma unroll
        for (int nt = 0; nt < 7; nt++) {
            float c0 = cs[(ngrp * 7 + nt) * 8 + 2 * tq];
            float c1 = cs[(ngrp * 7 + nt) * 8 + 2 * tq + 1];
            plo *= (1.f + __expf(acc[nt][0] + c0));
            plo *= (1.f + __expf(acc[nt][1] + c1));
            phi *= (1.f + __expf(acc[nt][2] + c0));
            phi *= (1.f + __expf(acc[nt][3] + c1));
        }
        float slo = __logf(plo);
        float shi = __logf(phi);
        slo += __shfl_xor_sync(0xFFFFFFFFu, slo, 1);
        slo += __shfl_xor_sync(0xFFFFFFFFu, slo, 2);
        shi += __shfl_xor_sync(0xFFFFFFFFu, shi, 1);
        shi += __shfl_xor_sync(0xFFFFFFFFu, shi, 2);
        if (tq == 0) {
            s_red[ngrp][m0 + g] = slo;
            s_red[ngrp][m0 + g + 8] = shi;
        }
    }
    __syncthreads();

    // --- per-row combine (+ target slot), block + grid reduce ---
    if (tid < MROWS) {
        float x0 = s_tdot[tid] + s_xc[tid];
        s_fin[tid] = s_red[0][tid] + s_red[1][tid] + softplus_exact(x0) - x0;
    }
    __syncthreads();
    if (tid < 32) {
        float s = s_fin[tid] + s_fin[tid + 32];
        s += __shfl_xor_sync(0xFFFFFFFFu, s, 16);
        s += __shfl_xor_sync(0xFFFFFFFFu, s, 8);
        s += __shfl_xor_sync(0xFFFFFFFFu, s, 4);
        s += __shfl_xor_sync(0xFFFFFFFFu, s, 2);
        s += __shfl_xor_sync(0xFFFFFFFFu, s, 1);
        if (lane == 0) {
            g_part[blockIdx.x] = s;
            __threadfence();
            int old = atomicAdd(&g_ctr, 1);
            s_flag = (old == NBLK - 1);
        }
        __syncwarp();
        if (s_flag) {                     // last block: warp-parallel final sum
            __threadfence();
            float t = 0.f;
#pragma unroll
            for (int k = 0; k < NBLK / 32; k++)
                t += *((volatile float*)&g_part[lane + 32 * k]);
            t += __shfl_xor_sync(0xFFFFFFFFu, t, 16);
            t += __shfl_xor_sync(0xFFFFFFFFu, t, 8);
            t += __shfl_xor_sync(0xFFFFFFFFu, t, 4);
            t += __shfl_xor_sync(0xFFFFFFFFu, t, 2);
            t += __shfl_xor_sync(0xFFFFFFFFu, t, 1);
            if (lane == 0) {
                out[0] = t * (1.0f / (float)BLROWS);
                g_ctr = 0;                // reset for graph replay
            }
        }
    }
}

// ---------------------------------------------------------------------------
extern "C" void kernel_launch(void* const* d_in, const int* in_sizes, int n_in,
                              void* d_out, int out_size) {
    const float* inp  = (const float*)d_in[0];
    const float* emb  = (const float*)d_in[1];
    const float* bias = (const float*)d_in[2];
    const float* lpn  = (const float*)d_in[3];
    const int*   tgt  = (const int*)  d_in[4];
    const int*   nidx = (const int*)  d_in[5];
    float* out = (float*)d_out;

    const int DSM = 1024 + 2 * ASTAGE + 2 * BSTAGE;   // ~51.7 KB per CTA
    cudaFuncSetAttribute(mega_kernel, cudaFuncAttributeMaxDynamicSharedMemorySize, DSM);
    mega_kernel<<<NBLK, 256, DSM>>>(inp, emb, bias, lpn, tgt, nidx, out);
}

// round 7
// speedup vs baseline: 2.2454x; 1.0122x over previous
#include <cuda_runtime.h>
#include <cuda_bf16.h>
#include <math.h>
#include <stdint.h>

#define E_DIM 512
#define BLROWS 16384
#define NRR 100
#define NPAD 112                        // 14 n-tiles of 8
#define NORM_TERM 10.82490511970208f    // ln(50257)
#define LOG_NR 4.605170185988092f       // ln(100)
#define MROWS 64                        // rows per CTA
#define ASTR 144                        // smem row stride (72 bf16)
#define ASTAGE (MROWS * ASTR)           // 9216
#define BSTAGE (NPAD * ASTR)            // 16128
#define NBLK 256

__device__ __align__(16) __nv_bfloat16 g_bn[NPAD * E_DIM];  // bf16 noise emb, rows>=100 zero
__device__ float g_part[NBLK];
__device__ int   g_ctr = 0;             // self-resetting (graph-replay safe)

__device__ __forceinline__ uint32_t smem_u32(const void* p) {
    uint32_t a;
    asm("{ .reg .u64 t; cvta.to.shared.u64 t, %1; cvt.u32.u64 %0, t; }" : "=r"(a) : "l"(p));
    return a;
}
__device__ __forceinline__ void cp_async16(uint32_t dst, const void* src) {
    asm volatile("cp.async.cg.shared.global [%0], [%1], 16;" :: "r"(dst), "l"(src));
}
#define CP_COMMIT() asm volatile("cp.async.commit_group;" ::: "memory")
#define CP_WAIT1()  asm volatile("cp.async.wait_group 1;" ::: "memory")
__device__ __forceinline__ void ldmatrix_x4(uint32_t& r0, uint32_t& r1,
                                            uint32_t& r2, uint32_t& r3, uint32_t addr) {
    asm volatile("ldmatrix.sync.aligned.m8n8.x4.shared.b16 {%0,%1,%2,%3}, [%4];"
                 : "=r"(r0), "=r"(r1), "=r"(r2), "=r"(r3) : "r"(addr));
}
__device__ __forceinline__ void ldmatrix_x2(uint32_t& r0, uint32_t& r1, uint32_t addr) {
    asm volatile("ldmatrix.sync.aligned.m8n8.x2.shared.b16 {%0,%1}, [%2];"
                 : "=r"(r0), "=r"(r1) : "r"(addr));
}
__device__ __forceinline__ void mma16816(float* d, const uint32_t* a,
                                         uint32_t b0, uint32_t b1) {
    asm volatile("mma.sync.aligned.m16n8k16.row.col.f32.bf16.bf16.f32 "
                 "{%0,%1,%2,%3}, {%4,%5,%6,%7}, {%8,%9}, {%0,%1,%2,%3};"
                 : "+f"(d[0]), "+f"(d[1]), "+f"(d[2]), "+f"(d[3])
                 : "r"(a[0]), "r"(a[1]), "r"(a[2]), "r"(a[3]), "r"(b0), "r"(b1));
}
__device__ __forceinline__ float softplus_exact(float x) {
    return fmaxf(x, 0.0f) + log1pf(expf(-fabsf(x)));
}
__device__ __forceinline__ uint2 cvt_bf16x4(float4 v) {
    __nv_bfloat162 p0 = __float22bfloat162_rn(make_float2(v.x, v.y));
    __nv_bfloat162 p1 = __float22bfloat162_rn(make_float2(v.z, v.w));
    uint2 r;
    r.x = *reinterpret_cast<uint32_t*>(&p0);
    r.y = *reinterpret_cast<uint32_t*>(&p1);
    return r;
}

// ---------------------------------------------------------------------------
// Prep: noise emb -> bf16 table [NPAD][512], padded rows zero.
// ---------------------------------------------------------------------------
__global__ void prep_kernel(const float* __restrict__ emb,
                            const int* __restrict__ nidx) {
    int idx = blockIdx.x * blockDim.x + threadIdx.x;   // over NPAD*128 quads
    if (idx >= NPAD * 128) return;
    int n = idx >> 7;
    int q = idx & 127;
    float4 v = make_float4(0.f, 0.f, 0.f, 0.f);
    if (n < NRR) {
        int t = nidx[n];
        v = *(const float4*)(emb + (size_t)t * E_DIM + q * 4);
    }
    *(uint2*)((char*)g_bn + (size_t)n * 1024 + q * 8) = cvt_bf16x4(v);
}

// ---------------------------------------------------------------------------
// Main: 64-row CTAs, 256 threads, 2 CTAs/SM, 3-stage A+B rings,
// ONE barrier per chunk, cp.async B, A prefetch depth 2, fused everything.
// ---------------------------------------------------------------------------
__global__ void __launch_bounds__(256, 2)
mega_kernel(const float* __restrict__ inp,
            const float* __restrict__ emb,
            const float* __restrict__ bias,
            const float* __restrict__ lpn,
            const int*   __restrict__ tgt,
            const int*   __restrict__ nidx,
            float* __restrict__ out) {
    extern __shared__ char dsm[];
    __shared__ float cs[NPAD];
    __shared__ int   s_t[MROWS];
    __shared__ float s_xc[MROWS];
    __shared__ float s_tdot[MROWS];
    __shared__ float s_red[2][MROWS];
    __shared__ float s_fin[MROWS];
    __shared__ int   s_flag;

    const int tid = threadIdx.x;
    const int lane = tid & 31;
    const int row0 = blockIdx.x * MROWS;

    const uint32_t db = smem_u32(dsm);
    const uint32_t abase = (db + 1023u) & ~1023u;
    const uint32_t bbase = abase + 3 * ASTAGE;
    char* ap = dsm + (abase - db);

    if (tid < NPAD) {
        int nv = (tid < NRR) ? nidx[tid] : -1;
        cs[tid] = (tid < NRR) ? (bias[nv] - NORM_TERM - lpn[nv] - LOG_NR) : -1e30f;
    }
    if (tid >= 128 && tid < 128 + MROWS) {
        int r = tid - 128;
        int t = tgt[row0 + r];
        s_t[r] = t;
        s_xc[r] = bias[t] - NORM_TERM - lpn[t] - LOG_NR;
    }
    __syncthreads();

    // ---------------- per-thread layout ----------------
    const int l4 = tid & 15;
    const int rg = tid >> 4;
    const float* ipt = inp + (size_t)(row0 + rg) * E_DIM + l4 * 4;
    uint32_t eoff[4];
#pragma unroll
    for (int i = 0; i < 4; i++)
        eoff[i] = (uint32_t)s_t[rg + 16 * i] * (E_DIM * 4) + l4 * 16;
    const uint32_t asts = rg * ASTR + l4 * 8;

    // B cp.async slots: idx = tid + 256*i, i<4, valid if idx<896 (=NPAD*8)
    uint32_t bdst[4];     // dst offset within a B stage
    uint32_t bsrc[4];     // src byte offset within g_bn for chunk 0
    int bok[4];
#pragma unroll
    for (int i = 0; i < 4; i++) {
        int idx = tid + 256 * i;
        bok[i] = (idx < NPAD * 8);
        int n = idx >> 3, sl = idx & 7;
        bdst[i] = (uint32_t)n * ASTR + sl * 16;
        bsrc[i] = (uint32_t)n * 1024 + sl * 16;
    }
    const char* bn = (const char*)g_bn;

    // MMA fragment addressing (proven mapping)
    const int m0 = (tid >> 5 & 3) * 16;
    const int ngrp = tid >> 7;
    const uint32_t a_woff = (uint32_t)(m0 + (lane & 15)) * ASTR + ((lane >> 4) << 4);
    const uint32_t b_woff = (uint32_t)(ngrp * 56 + (lane & 7) + ((lane >> 4) << 3)) * ASTR
                          + (((lane >> 3) & 1) << 4);
    const uint32_t b2_woff = (uint32_t)(ngrp * 56 + 48 + (lane & 7)) * ASTR
                           + (((lane >> 3) & 1) << 4);

    float acc[7][4];
#pragma unroll
    for (int n = 0; n < 7; n++)
#pragma unroll
        for (int j = 0; j < 4; j++) acc[n][j] = 0.f;
    float tacc[4] = {0.f, 0.f, 0.f, 0.f};

    // ---------------- prologue ----------------
    float4 va[2][4], ve[2][4];
#pragma unroll
    for (int s = 0; s < 2; s++)
#pragma unroll
        for (int i = 0; i < 4; i++) {
            va[s][i] = *(const float4*)(ipt + s * 64 + i * (16 * E_DIM));
            ve[s][i] = *(const float4*)((const char*)emb + eoff[i] + s * 256);
        }
#pragma unroll
    for (int s = 0; s < 2; s++) {           // cp.async B(0), B(1)
        uint32_t bs = bbase + s * BSTAGE;
#pragma unroll
        for (int i = 0; i < 4; i++)
            if (bok[i]) cp_async16(bs + bdst[i], bn + bsrc[i] + s * 128);
        CP_COMMIT();
    }

    // ---------------- main loop: 8 chunks, ONE sync each ----------------
#pragma unroll
    for (int c = 0; c < 8; c++) {
        const int set = c & 1;
        const int ast = c - (c >= 6 ? 6 : (c >= 3 ? 3 : 0));   // c % 3
        // STS A(c) + target-dot FMAs
        {
            char* adst = ap + ast * ASTAGE + asts;
#pragma unroll
            for (int i = 0; i < 4; i++) {
                tacc[i] += va[set][i].x * ve[set][i].x + va[set][i].y * ve[set][i].y
                         + va[set][i].z * ve[set][i].z + va[set][i].w * ve[set][i].w;
                *(uint2*)(adst + i * (16 * ASTR)) = cvt_bf16x4(va[set][i]);
            }
        }
        // LDG A(c+2) into regset set (2-iteration cover)
        if (c < 6) {
            const int ko = (c + 2) * 64;
#pragma unroll
            for (int i = 0; i < 4; i++) {
                va[set][i] = *(const float4*)(ipt + ko + i * (16 * E_DIM));
                ve[set][i] = *(const float4*)((const char*)emb + eoff[i] + ko * 4);
            }
        }
        CP_WAIT1();          // B(c) landed (own copies)
        __syncthreads();     // all warps: STS A(c) + B(c) visible; MMA(c-1) done
        // cp.async B(c+2) (safe: stage (c+2)%3 = (c-1)%3, MMA(c-1) done by all)
        if (c < 6) {
            const int bst2 = c - (c >= 4 ? 4 : 1);   // (c+2) % 3
            uint32_t bs = bbase + bst2 * BSTAGE;
            const char* src = bn + (c + 2) * 128;
#pragma unroll
            for (int i = 0; i < 4; i++)
                if (bok[i]) cp_async16(bs + bdst[i], src + bsrc[i]);
        }
        CP_COMMIT();         // always commit (empty ok) to keep group counting
        // MMA chunk c
        {
            const uint32_t ab = abase + ast * ASTAGE + a_woff;
            const uint32_t bb = bbase + ast * BSTAGE + b_woff;
            const uint32_t bb2 = bbase + ast * BSTAGE + b2_woff;
#pragma unroll
            for (int k0 = 0; k0 < 4; k0++) {
                uint32_t a[4];
                ldmatrix_x4(a[0], a[1], a[2], a[3], ab + k0 * 32);
#pragma unroll
                for (int p = 0; p < 3; p++) {
                    uint32_t b0, b1, b2, b3;
                    ldmatrix_x4(b0, b1, b2, b3, bb + p * (16 * ASTR) + k0 * 32);
                    mma16816(acc[p * 2], a, b0, b1);
                    mma16816(acc[p * 2 + 1], a, b2, b3);
                }
                uint32_t b0, b1;
                ldmatrix_x2(b0, b1, bb2 + k0 * 32);
                mma16816(acc[6], a, b0, b1);
            }
        }
    }

    // --- finish exact target dots ---
#pragma unroll
    for (int i = 0; i < 4; i++) {
        float v = tacc[i];
        v += __shfl_xor_sync(0xFFFFFFFFu, v, 8);
        v += __shfl_xor_sync(0xFFFFFFFFu, v, 4);
        v += __shfl_xor_sync(0xFFFFFFFFu, v, 2);
        v += __shfl_xor_sync(0xFFFFFFFFu, v, 1);
        if (l4 == 0) s_tdot[rg + 16 * i] = v;
    }

    // --- softplus epilogue (product trick; noise x <= -1.8 always) ---
    {
        const int g = lane >> 2;
        const int tq = lane & 3;
        float plo = 1.f, phi = 1.f;
#pragma unroll
        for (int nt = 0; nt < 7; nt++) {
            float c0 = cs[(ngrp * 7 + nt) * 8 + 2 * tq];
            float c1 = cs[(ngrp * 7 + nt) * 8 + 2 * tq + 1];
            plo *= (1.f + __expf(acc[nt][0] + c0));
            plo *= (1.f + __expf(acc[nt][1] + c1));
            phi *= (1.f + __expf(acc[nt][2] + c0));
            phi *= (1.f + __expf(acc[nt][3] + c1));
        }
        float slo = __logf(plo);
        float shi = __logf(phi);
        slo += __shfl_xor_sync(0xFFFFFFFFu, slo, 1);
        slo += __shfl_xor_sync(0xFFFFFFFFu, slo, 2);
        shi += __shfl_xor_sync(0xFFFFFFFFu, shi, 1);
        shi += __shfl_xor_sync(0xFFFFFFFFu, shi, 2);
        if (tq == 0) {
            s_red[ngrp][m0 + g] = slo;
            s_red[ngrp][m0 + g + 8] = shi;
        }
    }
    __syncthreads();

    // --- per-row combine (+ target slot), block + grid reduce ---
    if (tid < MROWS) {
        float x0 = s_tdot[tid] + s_xc[tid];
        s_fin[tid] = s_red[0][tid] + s_red[1][tid] + softplus_exact(x0) - x0;
    }
    __syncthreads();
    if (tid < 32) {
        float s = s_fin[tid] + s_fin[tid + 32];
        s += __shfl_xor_sync(0xFFFFFFFFu, s, 16);
        s += __shfl_xor_sync(0xFFFFFFFFu, s, 8);
        s += __shfl_xor_sync(0xFFFFFFFFu, s, 4);
        s += __shfl_xor_sync(0xFFFFFFFFu, s, 2);
        s += __shfl_xor_sync(0xFFFFFFFFu, s, 1);
        if (lane == 0) {
            g_part[blockIdx.x] = s;
            __threadfence();
            int old = atomicAdd(&g_ctr, 1);
            s_flag = (old == NBLK - 1);
        }
        __syncwarp();
        if (s_flag) {
            __threadfence();
            float t = 0.f;
#pragma unroll
            for (int k = 0; k < NBLK / 32; k++)
                t += *((volatile float*)&g_part[lane + 32 * k]);
            t += __shfl_xor_sync(0xFFFFFFFFu, t, 16);
            t += __shfl_xor_sync(0xFFFFFFFFu, t, 8);
            t += __shfl_xor_sync(0xFFFFFFFFu, t, 4);
            t += __shfl_xor_sync(0xFFFFFFFFu, t, 2);
            t += __shfl_xor_sync(0xFFFFFFFFu, t, 1);
            if (lane == 0) {
                out[0] = t * (1.0f / (float)BLROWS);
                g_ctr = 0;
            }
        }
    }
}

// ---------------------------------------------------------------------------
extern "C" void kernel_launch(void* const* d_in, const int* in_sizes, int n_in,
                              void* d_out, int out_size) {
    const float* inp  = (const float*)d_in[0];
    const float* emb  = (const float*)d_in[1];
    const float* bias = (const float*)d_in[2];
    const float* lpn  = (const float*)d_in[3];
    const int*   tgt  = (const int*)  d_in[4];
    const int*   nidx = (const int*)  d_in[5];
    float* out = (float*)d_out;

    const int DSM = 1024 + 3 * ASTAGE + 3 * BSTAGE;   // ~77 KB per CTA
    cudaFuncSetAttribute(mega_kernel, cudaFuncAttributeMaxDynamicSharedMemorySize, DSM);

    prep_kernel<<<(NPAD * 128 + 255) / 256, 256>>>(emb, nidx);
    mega_kernel<<<NBLK, 256, DSM>>>(inp, emb, bias, lpn, tgt, nidx, out);
}